// round 15
// baseline (speedup 1.0000x reference)
#include <cuda_runtime.h>
#include <cuda_fp16.h>
#include <math.h>
#include <stdint.h>

#define DM 3072
#define BB 2
#define SSEQ 1024
#define NH 24
#define HD 128
#define MROWS (BB*SSEQ)   // 2048

// Scratch (device globals: no allocations allowed)
__device__ float  g_q[MROWS*DM];
__device__ float  g_k[MROWS*DM];
__device__ __half g_xh[MROWS*DM];   // hidden fp16, later reused as q-hat fp16
__device__ __half g_kh[MROWS*DM];
__device__ __half g_vh[MROWS*DM];
__device__ __half g_aoh[MROWS*DM];

__device__ __forceinline__ uint32_t smem_u32(const void* p) {
    uint32_t a;
    asm("{ .reg .u64 t; cvta.to.shared.u64 t, %1; cvt.u32.u64 %0, t; }"
        : "=r"(a) : "l"(p));
    return a;
}

__device__ __forceinline__ float fexp2(float x) {
    float y;
    asm("ex2.approx.f32 %0, %1;" : "=f"(y) : "f"(x));
    return y;
}

__device__ __forceinline__ uint32_t h2exp2_bits(uint32_t x) {
    uint32_t y;
    asm("ex2.approx.f16x2 %0, %1;" : "=r"(y) : "r"(x));
    return y;
}

__device__ __forceinline__ void mma_f16(float c[4],
    uint32_t a0, uint32_t a1, uint32_t a2, uint32_t a3,
    uint32_t b0, uint32_t b1)
{
    asm volatile(
        "mma.sync.aligned.m16n8k16.row.col.f32.f16.f16.f32 "
        "{%0,%1,%2,%3}, {%4,%5,%6,%7}, {%8,%9}, {%0,%1,%2,%3};"
        : "+f"(c[0]), "+f"(c[1]), "+f"(c[2]), "+f"(c[3])
        : "r"(a0), "r"(a1), "r"(a2), "r"(a3), "r"(b0), "r"(b1));
}

__device__ __forceinline__ void ldsm_x4(
    uint32_t& r0, uint32_t& r1, uint32_t& r2, uint32_t& r3, uint32_t addr)
{
    asm volatile("ldmatrix.sync.aligned.m8n8.x4.shared.b16 {%0,%1,%2,%3}, [%4];"
        : "=r"(r0), "=r"(r1), "=r"(r2), "=r"(r3) : "r"(addr));
}

__device__ __forceinline__ void ldsm_x4_t(
    uint32_t& r0, uint32_t& r1, uint32_t& r2, uint32_t& r3, uint32_t addr)
{
    asm volatile("ldmatrix.sync.aligned.m8n8.x4.trans.shared.b16 {%0,%1,%2,%3}, [%4];"
        : "=r"(r0), "=r"(r1), "=r"(r2), "=r"(r3) : "r"(addr));
}

__device__ __forceinline__ void cp_async16(uint32_t saddr, const void* gptr) {
    asm volatile("cp.async.cg.shared.global [%0], [%1], 16;"
        :: "r"(saddr), "l"(gptr) : "memory");
}
#define CP_COMMIT() asm volatile("cp.async.commit_group;" ::: "memory")
#define CP_WAIT2()  asm volatile("cp.async.wait_group 2;" ::: "memory")
#define CP_WAIT1()  asm volatile("cp.async.wait_group 1;" ::: "memory")

__device__ __forceinline__ void red_add_f32(float* p, float v) {
    asm volatile("red.global.add.f32 [%0], %1;" :: "l"(p), "f"(v) : "memory");
}

// ---------------------------------------------------------------------------
// fp32 -> fp16 conversion for hidden (2-element ILP)
// ---------------------------------------------------------------------------
__global__ __launch_bounds__(256) void cvt_f32_f16(
    const float* __restrict__ src, __half* __restrict__ dst, int n4h)
{
    int i = blockIdx.x * blockDim.x + threadIdx.x;
    if (i < n4h) {
        float4 v0 = ((const float4*)src)[i];
        float4 v1 = ((const float4*)src)[i + n4h];
        __half2 a0 = __floats2half2_rn(v0.x, v0.y);
        __half2 a1 = __floats2half2_rn(v0.z, v0.w);
        __half2 b0 = __floats2half2_rn(v1.x, v1.y);
        __half2 b1 = __floats2half2_rn(v1.z, v1.w);
        uint2 o0 = {*(uint32_t*)&a0, *(uint32_t*)&a1};
        uint2 o1 = {*(uint32_t*)&b0, *(uint32_t*)&b1};
        ((uint2*)dst)[i]       = o0;
        ((uint2*)dst)[i + n4h] = o1;
    }
}

// ---------------------------------------------------------------------------
// fp16xfp32 GEMM: A (X) fp16 via cp.async 4-stage; B (weights) fp32 via
// LDG+cvt+STS register double-buffer. CTA 128x128x32k, one sync per k-tile.
// Smem: A stages 4x10240B, then B buffers 2x10240B. Total 61440B.
// ---------------------------------------------------------------------------
#define ASTAGEB 10240u
#define BBASE   40960u
#define GEMM_SMEM 61440

template<bool REDUCE>
__global__ __launch_bounds__(256, 2) void f16_gemm_kernel(
    const __half* __restrict__ X,
    const float* __restrict__ Wa, const float* __restrict__ Wb, const float* __restrict__ Wc,
    float* __restrict__ Ya, float* __restrict__ Yb, __half* __restrict__ Yc)
{
    extern __shared__ char smraw[];
    const uint32_t smb = smem_u32(smraw);

    const int t    = threadIdx.x;
    const int lane = t & 31;
    const int w    = t >> 5;
    const int warp_m = (w >> 1) * 32;
    const int warp_n = (w & 1) * 64;
    const int bx   = blockIdx.x;
    const int wsel = bx / 24;
    const float* W = (wsel == 0) ? Wa : ((wsel == 1) ? Wb : Wc);
    const int bm = blockIdx.y * 128;
    const int bn = (bx - wsel * 24) * 128;

    const int nkt = (DM / 32) / gridDim.z;       // 96 or 32
    const int kh0 = blockIdx.z * nkt * 32;

    // staging maps: thread -> row t>>1, k-halves (t&1)*16
    const int arow = t >> 1;
    const int kh16 = (t & 1) * 16;
    const __half* xp = X + (size_t)(bm + arow) * DM + kh0 + kh16;
    const float*  wp = W + (size_t)(bn + arow) * DM + kh0 + kh16;
    const uint32_t srow = (uint32_t)arow * 80u + (uint32_t)kh16 * 2u;

    const int l7 = lane & 7;
    const int aArow = warp_m + ((lane >> 3) & 1) * 8 + l7;
    const int aAkh  = (lane >> 4) * 8;
    uint32_t offA[2];
    #pragma unroll
    for (int mi = 0; mi < 2; mi++)
        offA[mi] = (uint32_t)(aArow + mi * 16) * 80u + (uint32_t)aAkh * 2u;
    const int aBn  = warp_n + (lane >> 4) * 8 + l7;
    const int aBkh = ((lane >> 3) & 1) * 8;
    uint32_t offB[4];
    #pragma unroll
    for (int np = 0; np < 4; np++)
        offB[np] = BBASE + (uint32_t)(aBn + np * 16) * 80u + (uint32_t)aBkh * 2u;

    float c[2][8][4];
    #pragma unroll
    for (int mi = 0; mi < 2; mi++)
        #pragma unroll
        for (int ni = 0; ni < 8; ni++)
            #pragma unroll
            for (int j = 0; j < 4; j++) c[mi][ni][j] = 0.f;

    const int qd = lane >> 2;
    const int qk = lane & 3;

    #define ISSUE_A(kt_, buf_) do { \
        const uint32_t sa = smb + (uint32_t)(buf_) * ASTAGEB + srow; \
        const __half* xg = xp + (kt_) * 32; \
        cp_async16(sa,       xg); \
        cp_async16(sa + 16u, xg + 8); \
    } while (0)

    // B staging: 16 fp32 -> 16 halves (2 uint4)
    uint4 bst0, bst1;
    #define BLOAD(kt_) do { \
        const float* wg = wp + (kt_) * 32; \
        float4 f0 = *(const float4*)(wg); \
        float4 f1 = *(const float4*)(wg + 4); \
        float4 f2 = *(const float4*)(wg + 8); \
        float4 f3 = *(const float4*)(wg + 12); \
        __half2 h0 = __floats2half2_rn(f0.x, f0.y); \
        __half2 h1 = __floats2half2_rn(f0.z, f0.w); \
        __half2 h2 = __floats2half2_rn(f1.x, f1.y); \
        __half2 h3 = __floats2half2_rn(f1.z, f1.w); \
        __half2 h4 = __floats2half2_rn(f2.x, f2.y); \
        __half2 h5 = __floats2half2_rn(f2.z, f2.w); \
        __half2 h6 = __floats2half2_rn(f3.x, f3.y); \
        __half2 h7 = __floats2half2_rn(f3.z, f3.w); \
        bst0.x = *(uint32_t*)&h0; bst0.y = *(uint32_t*)&h1; \
        bst0.z = *(uint32_t*)&h2; bst0.w = *(uint32_t*)&h3; \
        bst1.x = *(uint32_t*)&h4; bst1.y = *(uint32_t*)&h5; \
        bst1.z = *(uint32_t*)&h6; bst1.w = *(uint32_t*)&h7; \
    } while (0)

    #define BSTORE(buf_) do { \
        char* bp = smraw + BBASE + (uint32_t)(buf_) * ASTAGEB + srow; \
        *(uint4*)(bp)       = bst0; \
        *(uint4*)(bp + 16u) = bst1; \
    } while (0)

    ISSUE_A(0, 0); CP_COMMIT();
    ISSUE_A(1, 1); CP_COMMIT();
    ISSUE_A(2, 2); CP_COMMIT();
    BLOAD(0); BSTORE(0);

    for (int kt = 0; kt < nkt; kt++) {
        CP_WAIT2();        // A stage kt landed
        __syncthreads();   // A visible; B[kt&1] stores visible; prior reads done

        const int nk3 = kt + 3;
        if (nk3 < nkt) ISSUE_A(nk3, nk3 & 3);
        CP_COMMIT();

        if (kt + 1 < nkt) BLOAD(kt + 1);

        const uint32_t stA = smb + (uint32_t)(kt & 3) * ASTAGEB;
        const uint32_t bB  = (uint32_t)(kt & 1) * ASTAGEB;
        #pragma unroll
        for (int ks = 0; ks < 2; ks++) {
            const uint32_t koff = (uint32_t)ks * 32u;
            uint32_t a[2][4];
            ldsm_x4(a[0][0], a[0][1], a[0][2], a[0][3], stA + offA[0] + koff);
            ldsm_x4(a[1][0], a[1][1], a[1][2], a[1][3], stA + offA[1] + koff);
            #pragma unroll
            for (int np = 0; np < 4; np++) {
                uint32_t b0, b1, b2, b3;
                ldsm_x4(b0, b1, b2, b3, smb + bB + offB[np] + koff);
                mma_f16(c[0][2*np],   a[0][0], a[0][1], a[0][2], a[0][3], b0, b1);
                mma_f16(c[1][2*np],   a[1][0], a[1][1], a[1][2], a[1][3], b0, b1);
                mma_f16(c[0][2*np+1], a[0][0], a[0][1], a[0][2], a[0][3], b2, b3);
                mma_f16(c[1][2*np+1], a[1][0], a[1][1], a[1][2], a[1][3], b2, b3);
            }
        }

        if (kt + 1 < nkt) BSTORE((kt + 1) & 1);
    }
    #undef ISSUE_A
    #undef BLOAD
    #undef BSTORE

    if (REDUCE) {
        float* Y = Ya;
        #pragma unroll
        for (int mi = 0; mi < 2; mi++) {
            #pragma unroll
            for (int ni = 0; ni < 8; ni++) {
                const int row = bm + warp_m + mi*16 + qd;
                const int col = bn + warp_n + ni*8 + qk*2;
                float* p0 = Y + (size_t)row * DM + col;
                float* p1 = Y + (size_t)(row + 8) * DM + col;
                red_add_f32(p0,     c[mi][ni][0]);
                red_add_f32(p0 + 1, c[mi][ni][1]);
                red_add_f32(p1,     c[mi][ni][2]);
                red_add_f32(p1 + 1, c[mi][ni][3]);
            }
        }
    } else if (wsel < 2) {
        float* Y = wsel ? Yb : Ya;
        #pragma unroll
        for (int mi = 0; mi < 2; mi++) {
            #pragma unroll
            for (int ni = 0; ni < 8; ni++) {
                const int row = bm + warp_m + mi*16 + qd;
                const int col = bn + warp_n + ni*8 + qk*2;
                float2 v0 = {c[mi][ni][0], c[mi][ni][1]};
                float2 v1 = {c[mi][ni][2], c[mi][ni][3]};
                *(float2*)(Y + (size_t)row * DM + col)       = v0;
                *(float2*)(Y + (size_t)(row + 8) * DM + col) = v1;
            }
        }
    } else {
        #pragma unroll
        for (int mi = 0; mi < 2; mi++) {
            #pragma unroll
            for (int ni = 0; ni < 8; ni++) {
                const int row = bm + warp_m + mi*16 + qd;
                const int col = bn + warp_n + ni*8 + qk*2;
                __half2 h0 = __floats2half2_rn(c[mi][ni][0], c[mi][ni][1]);
                __half2 h1 = __floats2half2_rn(c[mi][ni][2], c[mi][ni][3]);
                *(__half2*)(Yc + (size_t)row * DM + col)       = h0;
                *(__half2*)(Yc + (size_t)(row + 8) * DM + col) = h1;
            }
        }
    }
}

// ---------------------------------------------------------------------------
// Fused RMSNorm + RoPE v2 (unchanged).
// ---------------------------------------------------------------------------
__global__ __launch_bounds__(256) void norm_rope_kernel(
    const float* __restrict__ q, const float* __restrict__ k,
    __half* __restrict__ qh, __half* __restrict__ kh,
    const float* __restrict__ rope,
    const float* __restrict__ wq, const float* __restrict__ wk)
{
    __shared__ float cs_s[128], sn_s[128];
    const int row = blockIdx.x;
    const int s   = row & (SSEQ - 1);
    const int t   = threadIdx.x;

    if (t < 128) {
        float fr = rope[s * HD + t];
        float sn, cs;
        sincosf(fr, &sn, &cs);
        cs_s[t] = cs;
        sn_s[t] = sn;
    }
    __syncthreads();

    const int w    = t >> 5;
    const int lane = t & 31;
    const int h    = blockIdx.y * 8 + w;
    const int d4   = lane * 4;
    const size_t idx = (size_t)row * DM + h * HD + d4;
    const bool lo  = (lane < 16);

    float4 c4 = *(float4*)&cs_s[d4];
    float4 s4 = *(float4*)&sn_s[d4];

    #pragma unroll
    for (int which = 0; which < 2; which++) {
        const float* src = which ? k : q;
        __half* dst      = which ? kh : qh;
        const float* wn  = which ? wk : wq;

        float4 x = *(const float4*)(src + idx);
        float ss = x.x*x.x + x.y*x.y + x.z*x.z + x.w*x.w;
        #pragma unroll
        for (int o = 16; o > 0; o >>= 1)
            ss += __shfl_xor_sync(0xffffffffu, ss, o);
        float rs = rsqrtf(ss * (1.f/128.f) + 1e-6f);
        float4 wv = *(const float4*)(wn + d4);
        float xn0 = x.x * rs * wv.x;
        float xn1 = x.y * rs * wv.y;
        float xn2 = x.z * rs * wv.z;
        float xn3 = x.w * rs * wv.w;
        float p0 = __shfl_xor_sync(0xffffffffu, xn0, 16);
        float p1 = __shfl_xor_sync(0xffffffffu, xn1, 16);
        float p2 = __shfl_xor_sync(0xffffffffu, xn2, 16);
        float p3 = __shfl_xor_sync(0xffffffffu, xn3, 16);
        float r0 = lo ? -p0 : p0;
        float r1 = lo ? -p1 : p1;
        float r2 = lo ? -p2 : p2;
        float r3 = lo ? -p3 : p3;
        __half2 h0 = __floats2half2_rn(xn0 * c4.x + r0 * s4.x,
                                       xn1 * c4.y + r1 * s4.y);
        __half2 h1 = __floats2half2_rn(xn2 * c4.z + r2 * s4.z,
                                       xn3 * c4.w + r3 * s4.w);
        uint2 o = {*(uint32_t*)&h0, *(uint32_t*)&h1};
        *(uint2*)(dst + idx) = o;
    }
}

// ---------------------------------------------------------------------------
// fp16 flash attention (R13) + fused zeroing of the Wo output buffer.
// ---------------------------------------------------------------------------
#define STH 136
#define STB (STH*2)
#define ATT_SMEM ((64 + 128 + 128) * STH * 2)   // 87040

__global__ __launch_bounds__(128) void attn_kernel(
    const __half* __restrict__ Q, const __half* __restrict__ K,
    const __half* __restrict__ V, __half* __restrict__ O,
    float* __restrict__ outz)
{
    extern __shared__ char smraw[];
    __half* Qh = (__half*)smraw;
    const uint32_t sQ = smem_u32(Qh);
    const uint32_t sK0 = sQ + 64u * STB;
    const uint32_t sK1 = sQ + 128u * STB;
    const uint32_t sV0 = sQ + 192u * STB;
    const uint32_t sV1 = sQ + 256u * STB;

    const int t    = threadIdx.x;
    const int lane = t & 31;
    const int w    = t >> 5;
    const int qd   = lane >> 2;
    const int qk   = lane & 3;
    const int wm   = w * 16;

    const int qt = blockIdx.x;
    const int bh = blockIdx.y;
    const int b  = bh / NH;
    const int h  = bh % NH;
    const size_t base = (size_t)b * SSEQ * DM + (size_t)h * HD;
    const __half* qb = Q + base;
    const __half* kb = K + base;
    const __half* vb = V + base;
    const int q0 = qt * 64;

    const int l7   = lane & 7;
    const int arow = ((lane >> 3) & 1) * 8 + l7;
    const int akh  = (lane >> 4) * 8;
    const uint32_t aQ = sQ + (uint32_t)(wm + arow) * STB + (uint32_t)akh * 2u;
    const int bnr  = (lane >> 4) * 8 + l7;
    const int bkh  = ((lane >> 3) & 1) * 8;
    const uint32_t fK0 = sK0 + (uint32_t)bnr * STB + (uint32_t)bkh * 2u;
    const uint32_t fK1 = sK1 + (uint32_t)bnr * STB + (uint32_t)bkh * 2u;
    const uint32_t voff = (uint32_t)arow * STB + (uint32_t)((lane >> 4) * 8) * 2u;
    const uint32_t fV0 = sV0 + voff;
    const uint32_t fV1 = sV1 + voff;

    #define ATT_ISSUE(kt_, kbuf_, vbuf_) do { \
        const int k0_ = (kt_) * 64; \
        _Pragma("unroll") \
        for (int it = 0; it < 8; it++) { \
            const int f   = t + it * 128; \
            const int row = f >> 4; \
            const int ch  = f & 15; \
            const size_t g = (size_t)(k0_ + row) * DM + ch * 8; \
            const uint32_t so = (uint32_t)row * STB + (uint32_t)ch * 16u; \
            cp_async16((kbuf_) + so, kb + g); \
            cp_async16((vbuf_) + so, vb + g); \
        } \
    } while (0)

    ATT_ISSUE(0, sK0, sV0); CP_COMMIT();
    ATT_ISSUE(1, sK1, sV1); CP_COMMIT();

    // Zero this CTA's slice of the Wo output (hidden under cp.async latency).
    {
        float4* zp = (float4*)outz + ((size_t)bh * gridDim.x + qt) * 2048;
        const float4 z = {0.f, 0.f, 0.f, 0.f};
        #pragma unroll
        for (int it = 0; it < 16; it++)
            zp[t + it * 128] = z;
    }

    #pragma unroll
    for (int it = 0; it < 8; it++) {
        const int f   = t + it * 128;
        const int row = f >> 4;
        const int c8  = (f & 15) * 8;
        uint4 u = *(const uint4*)(qb + (size_t)(q0 + row) * DM + c8);
        *(uint4*)(Qh + row * STH + c8) = u;
    }
    __syncthreads();

    uint32_t qf[8][4];
    #pragma unroll
    for (int ks = 0; ks < 8; ks++)
        ldsm_x4(qf[ks][0], qf[ks][1], qf[ks][2], qf[ks][3],
                aQ + (uint32_t)ks * 32u);

    float o[16][4];
    #pragma unroll
    for (int ni = 0; ni < 16; ni++)
        #pragma unroll
        for (int j = 0; j < 4; j++) o[ni][j] = 0.f;

    float m0 = -1e30f, m1 = -1e30f, l0 = 0.f, l1 = 0.f;
    const float scale2 = 0.12751744f;

    for (int kt = 0; kt < 16; kt++) {
        CP_WAIT1();
        __syncthreads();

        const uint32_t fK = (kt & 1) ? fK1 : fK0;
        const uint32_t fV = (kt & 1) ? fV1 : fV0;

        float cs[8][4];
        #pragma unroll
        for (int ni = 0; ni < 8; ni++)
            #pragma unroll
            for (int j = 0; j < 4; j++) cs[ni][j] = 0.f;

        #pragma unroll
        for (int ks = 0; ks < 8; ks++) {
            const uint32_t koff = (uint32_t)ks * 32u;
            #pragma unroll
            for (int p = 0; p < 4; p++) {
                uint32_t b0, b1, b2, b3;
                ldsm_x4(b0, b1, b2, b3, fK + (uint32_t)(p * 16) * STB + koff);
                mma_f16(cs[2*p],   qf[ks][0], qf[ks][1], qf[ks][2], qf[ks][3], b0, b1);
                mma_f16(cs[2*p+1], qf[ks][0], qf[ks][1], qf[ks][2], qf[ks][3], b2, b3);
            }
        }
        #pragma unroll
        for (int ni = 0; ni < 8; ni++) {
            cs[ni][0] *= scale2; cs[ni][1] *= scale2;
            cs[ni][2] *= scale2; cs[ni][3] *= scale2;
        }

        float t0 = -1e30f, t1 = -1e30f;
        #pragma unroll
        for (int ni = 0; ni < 8; ni++) {
            t0 = fmaxf(t0, fmaxf(cs[ni][0], cs[ni][1]));
            t1 = fmaxf(t1, fmaxf(cs[ni][2], cs[ni][3]));
        }
        t0 = fmaxf(t0, __shfl_xor_sync(0xffffffffu, t0, 1));
        t0 = fmaxf(t0, __shfl_xor_sync(0xffffffffu, t0, 2));
        t1 = fmaxf(t1, __shfl_xor_sync(0xffffffffu, t1, 1));
        t1 = fmaxf(t1, __shfl_xor_sync(0xffffffffu, t1, 2));
        const float mn0 = fmaxf(m0, t0);
        const float mn1 = fmaxf(m1, t1);
        const float al0 = fexp2(m0 - mn0);
        const float al1 = fexp2(m1 - mn1);

        uint32_t plo[8], phi[8];
        float ps0 = 0.f, ps1 = 0.f;
        #pragma unroll
        for (int ni = 0; ni < 8; ni++) {
            __half2 d0 = __floats2half2_rn(cs[ni][0] - mn0, cs[ni][1] - mn0);
            __half2 d1 = __floats2half2_rn(cs[ni][2] - mn1, cs[ni][3] - mn1);
            plo[ni] = h2exp2_bits(*(uint32_t*)&d0);
            phi[ni] = h2exp2_bits(*(uint32_t*)&d1);
            __half2 p0 = *(__half2*)&plo[ni];
            __half2 p1 = *(__half2*)&phi[ni];
            ps0 += __low2float(p0) + __high2float(p0);
            ps1 += __low2float(p1) + __high2float(p1);
        }
        ps0 += __shfl_xor_sync(0xffffffffu, ps0, 1);
        ps0 += __shfl_xor_sync(0xffffffffu, ps0, 2);
        ps1 += __shfl_xor_sync(0xffffffffu, ps1, 1);
        ps1 += __shfl_xor_sync(0xffffffffu, ps1, 2);
        l0 = l0 * al0 + ps0;
        l1 = l1 * al1 + ps1;
        m0 = mn0;
        m1 = mn1;

        #pragma unroll
        for (int ni = 0; ni < 16; ni++) {
            o[ni][0] *= al0; o[ni][1] *= al0;
            o[ni][2] *= al1; o[ni][3] *= al1;
        }

        #pragma unroll
        for (int kc = 0; kc < 4; kc++) {
            const uint32_t a0 = plo[2*kc],   a1 = phi[2*kc];
            const uint32_t a2 = plo[2*kc+1], a3 = phi[2*kc+1];
            const uint32_t vro = (uint32_t)(kc * 16) * STB;
            #pragma unroll
            for (int np = 0; np < 8; np++) {
                uint32_t b0, b1, b2, b3;
                ldsm_x4_t(b0, b1, b2, b3, fV + vro + (uint32_t)np * 32u);
                mma_f16(o[2*np],   a0, a1, a2, a3, b0, b1);
                mma_f16(o[2*np+1], a0, a1, a2, a3, b2, b3);
            }
        }

        __syncthreads();
        if (kt + 2 < 16) {
            if (kt & 1) { ATT_ISSUE(kt + 2, sK1, sV1); }
            else        { ATT_ISSUE(kt + 2, sK0, sV0); }
        }
        CP_COMMIT();
    }
    #undef ATT_ISSUE

    const float inv0 = 1.f / l0;
    const float inv1 = 1.f / l1;
    #pragma unroll
    for (int ni = 0; ni < 16; ni++) {
        const int col = ni * 8 + 2 * qk;
        __half2 h0 = __floats2half2_rn(o[ni][0] * inv0, o[ni][1] * inv0);
        __half2 h1 = __floats2half2_rn(o[ni][2] * inv1, o[ni][3] * inv1);
        *(__half2*)(O + base + (size_t)(q0 + wm + qd)     * DM + col) = h0;
        *(__half2*)(O + base + (size_t)(q0 + wm + qd + 8) * DM + col) = h1;
    }
}

// ---------------------------------------------------------------------------
extern "C" void kernel_launch(void* const* d_in, const int* in_sizes, int n_in,
                              void* d_out, int out_size)
{
    const float* hidden = (const float*)d_in[0];
    const float* rope   = (const float*)d_in[1];
    const float* Wq     = (const float*)d_in[2];
    const float* Wk     = (const float*)d_in[3];
    const float* Wv     = (const float*)d_in[4];
    const float* Wo     = (const float*)d_in[5];
    const float* nqw    = (const float*)d_in[6];
    const float* nkw    = (const float*)d_in[7];
    float* out = (float*)d_out;

    float *q, *k;
    __half *xh, *kh, *vh, *aoh;
    cudaGetSymbolAddress((void**)&q,   g_q);
    cudaGetSymbolAddress((void**)&k,   g_k);
    cudaGetSymbolAddress((void**)&xh,  g_xh);
    cudaGetSymbolAddress((void**)&kh,  g_kh);
    cudaGetSymbolAddress((void**)&vh,  g_vh);
    cudaGetSymbolAddress((void**)&aoh, g_aoh);

    const int nX4 = MROWS * DM / 4;
    cvt_f32_f16<<<(nX4/2 + 255) / 256, 256>>>(hidden, xh, nX4/2);

    cudaFuncSetAttribute(f16_gemm_kernel<false>, cudaFuncAttributeMaxDynamicSharedMemorySize, GEMM_SMEM);
    cudaFuncSetAttribute(f16_gemm_kernel<true>,  cudaFuncAttributeMaxDynamicSharedMemorySize, GEMM_SMEM);
    cudaFuncSetAttribute(attn_kernel, cudaFuncAttributeMaxDynamicSharedMemorySize, ATT_SMEM);

    // Fused QKV projection: weights converted in-kernel; q,k fp32; v fp16
    f16_gemm_kernel<false><<<dim3(72, 16, 1), 256, GEMM_SMEM>>>(xh, Wq, Wk, Wv, q, k, vh);

    // Norm+RoPE: q,k fp32 -> fp16 (q-hat into xh)
    norm_rope_kernel<<<dim3(MROWS, NH/8), 256>>>(q, k, xh, kh, rope, nqw, nkw);

    // Attention (also zeros `out` for the reducing Wo GEMM)
    attn_kernel<<<dim3(SSEQ/64, BB*NH), 128, ATT_SMEM>>>(xh, kh, vh, aoh, out);

    // Output projection, k-split 3, atomic-add epilogue
    f16_gemm_kernel<true><<<dim3(24, 16, 3), 256, GEMM_SMEM>>>(aoh, Wo, Wo, Wo, out, out, aoh);
}

// round 16
// speedup vs baseline: 1.1771x; 1.1771x over previous
#include <cuda_runtime.h>
#include <cuda_fp16.h>
#include <math.h>
#include <stdint.h>

#define DM 3072
#define BB 2
#define SSEQ 1024
#define NH 24
#define HD 128
#define MROWS (BB*SSEQ)   // 2048

// Scratch (device globals: no allocations allowed)
__device__ float  g_q[MROWS*DM];
__device__ float  g_k[MROWS*DM];
__device__ __half g_xh[MROWS*DM];   // hidden fp16, later reused as q-hat fp16
__device__ __half g_kh[MROWS*DM];
__device__ __half g_vh[MROWS*DM];
__device__ __half g_aoh[MROWS*DM];
__device__ __half g_wqh[DM*DM];
__device__ __half g_wkh[DM*DM];
__device__ __half g_wvh[DM*DM];
__device__ __half g_woh[DM*DM];

__device__ __forceinline__ uint32_t smem_u32(const void* p) {
    uint32_t a;
    asm("{ .reg .u64 t; cvta.to.shared.u64 t, %1; cvt.u32.u64 %0, t; }"
        : "=r"(a) : "l"(p));
    return a;
}

__device__ __forceinline__ float fexp2(float x) {
    float y;
    asm("ex2.approx.f32 %0, %1;" : "=f"(y) : "f"(x));
    return y;
}

__device__ __forceinline__ uint32_t h2exp2_bits(uint32_t x) {
    uint32_t y;
    asm("ex2.approx.f16x2 %0, %1;" : "=r"(y) : "r"(x));
    return y;
}

__device__ __forceinline__ void mma_f16(float c[4],
    uint32_t a0, uint32_t a1, uint32_t a2, uint32_t a3,
    uint32_t b0, uint32_t b1)
{
    asm volatile(
        "mma.sync.aligned.m16n8k16.row.col.f32.f16.f16.f32 "
        "{%0,%1,%2,%3}, {%4,%5,%6,%7}, {%8,%9}, {%0,%1,%2,%3};"
        : "+f"(c[0]), "+f"(c[1]), "+f"(c[2]), "+f"(c[3])
        : "r"(a0), "r"(a1), "r"(a2), "r"(a3), "r"(b0), "r"(b1));
}

__device__ __forceinline__ void ldsm_x4(
    uint32_t& r0, uint32_t& r1, uint32_t& r2, uint32_t& r3, uint32_t addr)
{
    asm volatile("ldmatrix.sync.aligned.m8n8.x4.shared.b16 {%0,%1,%2,%3}, [%4];"
        : "=r"(r0), "=r"(r1), "=r"(r2), "=r"(r3) : "r"(addr));
}

__device__ __forceinline__ void ldsm_x4_t(
    uint32_t& r0, uint32_t& r1, uint32_t& r2, uint32_t& r3, uint32_t addr)
{
    asm volatile("ldmatrix.sync.aligned.m8n8.x4.trans.shared.b16 {%0,%1,%2,%3}, [%4];"
        : "=r"(r0), "=r"(r1), "=r"(r2), "=r"(r3) : "r"(addr));
}

__device__ __forceinline__ void cp_async16(uint32_t saddr, const void* gptr) {
    asm volatile("cp.async.cg.shared.global [%0], [%1], 16;"
        :: "r"(saddr), "l"(gptr) : "memory");
}
#define CP_COMMIT() asm volatile("cp.async.commit_group;" ::: "memory")
#define CP_WAIT2()  asm volatile("cp.async.wait_group 2;" ::: "memory")
#define CP_WAIT1()  asm volatile("cp.async.wait_group 1;" ::: "memory")

__device__ __forceinline__ void red_add_f32(float* p, float v) {
    asm volatile("red.global.add.f32 [%0], %1;" :: "l"(p), "f"(v) : "memory");
}

// ---------------------------------------------------------------------------
// fp32 -> fp16 conversions (2-element ILP)
// ---------------------------------------------------------------------------
__global__ __launch_bounds__(256) void cvt_f32_f16(
    const float* __restrict__ src, __half* __restrict__ dst, int n4h)
{
    int i = blockIdx.x * blockDim.x + threadIdx.x;
    if (i < n4h) {
        float4 v0 = ((const float4*)src)[i];
        float4 v1 = ((const float4*)src)[i + n4h];
        __half2 a0 = __floats2half2_rn(v0.x, v0.y);
        __half2 a1 = __floats2half2_rn(v0.z, v0.w);
        __half2 b0 = __floats2half2_rn(v1.x, v1.y);
        __half2 b1 = __floats2half2_rn(v1.z, v1.w);
        uint2 o0 = {*(uint32_t*)&a0, *(uint32_t*)&a1};
        uint2 o1 = {*(uint32_t*)&b0, *(uint32_t*)&b1};
        ((uint2*)dst)[i]       = o0;
        ((uint2*)dst)[i + n4h] = o1;
    }
}

__global__ __launch_bounds__(256) void cvt4_f32_f16(
    const float* __restrict__ s0, const float* __restrict__ s1,
    const float* __restrict__ s2, const float* __restrict__ s3,
    __half* __restrict__ d0, __half* __restrict__ d1,
    __half* __restrict__ d2, __half* __restrict__ d3, int n4)
{
    int base = blockIdx.x * blockDim.x + threadIdx.x;
    #pragma unroll
    for (int r = 0; r < 2; r++) {
        int i = base + r * ((4 * n4) / 2);
        int which = i / n4;
        int j = i - which * n4;
        const float* s = (which == 0) ? s0 : (which == 1) ? s1 : (which == 2) ? s2 : s3;
        __half* d      = (which == 0) ? d0 : (which == 1) ? d1 : (which == 2) ? d2 : d3;
        float4 v = ((const float4*)s)[j];
        __half2 h0 = __floats2half2_rn(v.x, v.y);
        __half2 h1 = __floats2half2_rn(v.z, v.w);
        uint2 o = {*(uint32_t*)&h0, *(uint32_t*)&h1};
        ((uint2*)d)[j] = o;
    }
}

__global__ __launch_bounds__(256) void zero_f32(float* __restrict__ p, int n4)
{
    int i = blockIdx.x * blockDim.x + threadIdx.x;
    if (i < n4) {
        float4 z = {0.f, 0.f, 0.f, 0.f};
        ((float4*)p)[i] = z;
    }
}

// ---------------------------------------------------------------------------
// fp16 GEMM, cp.async 4-stage pipeline, one sync per k-tile (R12, best).
// k-range split by blockIdx.z. REDUCE: fp32 red.add epilogue.
// ---------------------------------------------------------------------------
#define STAGEB 20480
#define NSTAGE 4
#define GEMM_SMEM (NSTAGE * STAGEB)   // 81920

template<bool REDUCE>
__global__ __launch_bounds__(256, 2) void f16_gemm_kernel(
    const __half* __restrict__ X,
    const __half* __restrict__ Wa, const __half* __restrict__ Wb, const __half* __restrict__ Wc,
    float* __restrict__ Ya, float* __restrict__ Yb, __half* __restrict__ Yc)
{
    extern __shared__ char smraw[];
    const uint32_t smb = smem_u32(smraw);

    const int t    = threadIdx.x;
    const int lane = t & 31;
    const int w    = t >> 5;
    const int warp_m = (w >> 1) * 32;
    const int warp_n = (w & 1) * 64;
    const int bx   = blockIdx.x;
    const int wsel = bx / 24;
    const __half* W = (wsel == 0) ? Wa : ((wsel == 1) ? Wb : Wc);
    const int bm = blockIdx.y * 128;
    const int bn = (bx - wsel * 24) * 128;

    const int nkt = (DM / 32) / gridDim.z;       // 96 or 32
    const int kh0 = blockIdx.z * nkt * 32;

    const int arow = t >> 1;
    const int kh16 = (t & 1) * 16;
    const __half* xp = X + (size_t)(bm + arow) * DM + kh0 + kh16;
    const __half* wp = W + (size_t)(bn + arow) * DM + kh0 + kh16;
    const uint32_t srow = (uint32_t)arow * 80u + (uint32_t)kh16 * 2u;

    const int l7 = lane & 7;
    const int aArow = warp_m + ((lane >> 3) & 1) * 8 + l7;
    const int aAkh  = (lane >> 4) * 8;
    uint32_t offA[2];
    #pragma unroll
    for (int mi = 0; mi < 2; mi++)
        offA[mi] = (uint32_t)(aArow + mi * 16) * 80u + (uint32_t)aAkh * 2u;
    const int aBn  = warp_n + (lane >> 4) * 8 + l7;
    const int aBkh = ((lane >> 3) & 1) * 8;
    uint32_t offB[4];
    #pragma unroll
    for (int np = 0; np < 4; np++)
        offB[np] = 10240u + (uint32_t)(aBn + np * 16) * 80u + (uint32_t)aBkh * 2u;

    float c[2][8][4];
    #pragma unroll
    for (int mi = 0; mi < 2; mi++)
        #pragma unroll
        for (int ni = 0; ni < 8; ni++)
            #pragma unroll
            for (int j = 0; j < 4; j++) c[mi][ni][j] = 0.f;

    const int qd = lane >> 2;
    const int qk = lane & 3;

    #define ISSUE(kt_, buf_) do { \
        const uint32_t sa = smb + (uint32_t)(buf_) * STAGEB + srow; \
        const __half* xg = xp + (kt_) * 32; \
        const __half* wg = wp + (kt_) * 32; \
        cp_async16(sa,           xg); \
        cp_async16(sa + 16u,     xg + 8); \
        cp_async16(sa + 10240u,      wg); \
        cp_async16(sa + 10240u + 16u, wg + 8); \
    } while (0)

    ISSUE(0, 0); CP_COMMIT();
    ISSUE(1, 1); CP_COMMIT();
    ISSUE(2, 2); CP_COMMIT();

    for (int kt = 0; kt < nkt; kt++) {
        const int buf = kt & 3;
        CP_WAIT2();
        __syncthreads();   // stage kt visible to all; prior iter compute done

        const int nk = kt + 3;
        if (nk < nkt) {
            ISSUE(nk, nk & 3);   // overwrites buf (kt-1)&3 — safe past the sync
        }
        CP_COMMIT();

        const uint32_t st = smb + (uint32_t)buf * STAGEB;
        #pragma unroll
        for (int ks = 0; ks < 2; ks++) {
            const uint32_t koff = (uint32_t)ks * 32u;
            uint32_t a[2][4];
            ldsm_x4(a[0][0], a[0][1], a[0][2], a[0][3], st + offA[0] + koff);
            ldsm_x4(a[1][0], a[1][1], a[1][2], a[1][3], st + offA[1] + koff);
            #pragma unroll
            for (int np = 0; np < 4; np++) {
                uint32_t b0, b1, b2, b3;
                ldsm_x4(b0, b1, b2, b3, st + offB[np] + koff);
                mma_f16(c[0][2*np],   a[0][0], a[0][1], a[0][2], a[0][3], b0, b1);
                mma_f16(c[1][2*np],   a[1][0], a[1][1], a[1][2], a[1][3], b0, b1);
                mma_f16(c[0][2*np+1], a[0][0], a[0][1], a[0][2], a[0][3], b2, b3);
                mma_f16(c[1][2*np+1], a[1][0], a[1][1], a[1][2], a[1][3], b2, b3);
            }
        }
    }
    #undef ISSUE

    if (REDUCE) {
        float* Y = Ya;
        #pragma unroll
        for (int mi = 0; mi < 2; mi++) {
            #pragma unroll
            for (int ni = 0; ni < 8; ni++) {
                const int row = bm + warp_m + mi*16 + qd;
                const int col = bn + warp_n + ni*8 + qk*2;
                float* p0 = Y + (size_t)row * DM + col;
                float* p1 = Y + (size_t)(row + 8) * DM + col;
                red_add_f32(p0,     c[mi][ni][0]);
                red_add_f32(p0 + 1, c[mi][ni][1]);
                red_add_f32(p1,     c[mi][ni][2]);
                red_add_f32(p1 + 1, c[mi][ni][3]);
            }
        }
    } else if (wsel < 2) {
        float* Y = wsel ? Yb : Ya;
        #pragma unroll
        for (int mi = 0; mi < 2; mi++) {
            #pragma unroll
            for (int ni = 0; ni < 8; ni++) {
                const int row = bm + warp_m + mi*16 + qd;
                const int col = bn + warp_n + ni*8 + qk*2;
                float2 v0 = {c[mi][ni][0], c[mi][ni][1]};
                float2 v1 = {c[mi][ni][2], c[mi][ni][3]};
                *(float2*)(Y + (size_t)row * DM + col)       = v0;
                *(float2*)(Y + (size_t)(row + 8) * DM + col) = v1;
            }
        }
    } else {
        #pragma unroll
        for (int mi = 0; mi < 2; mi++) {
            #pragma unroll
            for (int ni = 0; ni < 8; ni++) {
                const int row = bm + warp_m + mi*16 + qd;
                const int col = bn + warp_n + ni*8 + qk*2;
                __half2 h0 = __floats2half2_rn(c[mi][ni][0], c[mi][ni][1]);
                __half2 h1 = __floats2half2_rn(c[mi][ni][2], c[mi][ni][3]);
                *(__half2*)(Yc + (size_t)row * DM + col)       = h0;
                *(__half2*)(Yc + (size_t)(row + 8) * DM + col) = h1;
            }
        }
    }
}

// ---------------------------------------------------------------------------
// Fused RMSNorm + RoPE v2 (unchanged).
// ---------------------------------------------------------------------------
__global__ __launch_bounds__(256) void norm_rope_kernel(
    const float* __restrict__ q, const float* __restrict__ k,
    __half* __restrict__ qh, __half* __restrict__ kh,
    const float* __restrict__ rope,
    const float* __restrict__ wq, const float* __restrict__ wk)
{
    __shared__ float cs_s[128], sn_s[128];
    const int row = blockIdx.x;
    const int s   = row & (SSEQ - 1);
    const int t   = threadIdx.x;

    if (t < 128) {
        float fr = rope[s * HD + t];
        float sn, cs;
        sincosf(fr, &sn, &cs);
        cs_s[t] = cs;
        sn_s[t] = sn;
    }
    __syncthreads();

    const int w    = t >> 5;
    const int lane = t & 31;
    const int h    = blockIdx.y * 8 + w;
    const int d4   = lane * 4;
    const size_t idx = (size_t)row * DM + h * HD + d4;
    const bool lo  = (lane < 16);

    float4 c4 = *(float4*)&cs_s[d4];
    float4 s4 = *(float4*)&sn_s[d4];

    #pragma unroll
    for (int which = 0; which < 2; which++) {
        const float* src = which ? k : q;
        __half* dst      = which ? kh : qh;
        const float* wn  = which ? wk : wq;

        float4 x = *(const float4*)(src + idx);
        float ss = x.x*x.x + x.y*x.y + x.z*x.z + x.w*x.w;
        #pragma unroll
        for (int o = 16; o > 0; o >>= 1)
            ss += __shfl_xor_sync(0xffffffffu, ss, o);
        float rs = rsqrtf(ss * (1.f/128.f) + 1e-6f);
        float4 wv = *(const float4*)(wn + d4);
        float xn0 = x.x * rs * wv.x;
        float xn1 = x.y * rs * wv.y;
        float xn2 = x.z * rs * wv.z;
        float xn3 = x.w * rs * wv.w;
        float p0 = __shfl_xor_sync(0xffffffffu, xn0, 16);
        float p1 = __shfl_xor_sync(0xffffffffu, xn1, 16);
        float p2 = __shfl_xor_sync(0xffffffffu, xn2, 16);
        float p3 = __shfl_xor_sync(0xffffffffu, xn3, 16);
        float r0 = lo ? -p0 : p0;
        float r1 = lo ? -p1 : p1;
        float r2 = lo ? -p2 : p2;
        float r3 = lo ? -p3 : p3;
        __half2 h0 = __floats2half2_rn(xn0 * c4.x + r0 * s4.x,
                                       xn1 * c4.y + r1 * s4.y);
        __half2 h1 = __floats2half2_rn(xn2 * c4.z + r2 * s4.z,
                                       xn3 * c4.w + r3 * s4.w);
        uint2 o = {*(uint32_t*)&h0, *(uint32_t*)&h1};
        *(uint2*)(dst + idx) = o;
    }
}

// ---------------------------------------------------------------------------
// fp16 flash attention: FA2 register softmax, cp.async double-buffered
// 64-key K/V tiles, hoisted Q fragments. Q smem region is REUSED as K buffer
// 0 after the hoist -> smem 69632B -> 3 CTAs/SM.
// Buffers (64 rows x 272B each): B0 = ex-Q @0, B1 @17408, B2 @34816, B3 @52224.
// K tile kt -> (kt&1)? B1 : B0;  V tile kt -> (kt&1)? B3 : B2.
// ---------------------------------------------------------------------------
#define STH 136
#define STB (STH*2)
#define ATT_SMEM (4 * 64 * STB)   // 69632

__global__ __launch_bounds__(128, 3) void attn_kernel(
    const __half* __restrict__ Q, const __half* __restrict__ K,
    const __half* __restrict__ V, __half* __restrict__ O)
{
    extern __shared__ char smraw[];
    __half* Qh = (__half*)smraw;
    const uint32_t sQ = smem_u32(Qh);
    const uint32_t sB0 = sQ;                 // K buf0 (ex-Q)
    const uint32_t sB1 = sQ + 64u * STB;     // K buf1
    const uint32_t sB2 = sQ + 128u * STB;    // V buf0
    const uint32_t sB3 = sQ + 192u * STB;    // V buf1

    const int t    = threadIdx.x;
    const int lane = t & 31;
    const int w    = t >> 5;
    const int qd   = lane >> 2;
    const int qk   = lane & 3;
    const int wm   = w * 16;

    const int qt = blockIdx.x;
    const int bh = blockIdx.y;
    const int b  = bh / NH;
    const int h  = bh % NH;
    const size_t base = (size_t)b * SSEQ * DM + (size_t)h * HD;
    const __half* qb = Q + base;
    const __half* kb = K + base;
    const __half* vb = V + base;
    const int q0 = qt * 64;

    const int l7   = lane & 7;
    const int arow = ((lane >> 3) & 1) * 8 + l7;
    const int akh  = (lane >> 4) * 8;
    const uint32_t aQ = sQ + (uint32_t)(wm + arow) * STB + (uint32_t)akh * 2u;
    const int bnr  = (lane >> 4) * 8 + l7;
    const int bkh  = ((lane >> 3) & 1) * 8;
    const uint32_t fK0 = sB0 + (uint32_t)bnr * STB + (uint32_t)bkh * 2u;
    const uint32_t fK1 = sB1 + (uint32_t)bnr * STB + (uint32_t)bkh * 2u;
    const uint32_t voff = (uint32_t)arow * STB + (uint32_t)((lane >> 4) * 8) * 2u;
    const uint32_t fV0 = sB2 + voff;
    const uint32_t fV1 = sB3 + voff;

    #define ATT_ISSUE(kt_, kbuf_, vbuf_) do { \
        const int k0_ = (kt_) * 64; \
        _Pragma("unroll") \
        for (int it = 0; it < 8; it++) { \
            const int f   = t + it * 128; \
            const int row = f >> 4; \
            const int ch  = f & 15; \
            const size_t g = (size_t)(k0_ + row) * DM + ch * 8; \
            const uint32_t so = (uint32_t)row * STB + (uint32_t)ch * 16u; \
            cp_async16((kbuf_) + so, kb + g); \
            cp_async16((vbuf_) + so, vb + g); \
        } \
    } while (0)

    // Q tile: LDG -> STS, hoist fragments, then release the region for K buf0.
    #pragma unroll
    for (int it = 0; it < 8; it++) {
        const int f   = t + it * 128;
        const int row = f >> 4;
        const int c8  = (f & 15) * 8;
        uint4 u = *(const uint4*)(qb + (size_t)(q0 + row) * DM + c8);
        *(uint4*)(Qh + row * STH + c8) = u;
    }
    __syncthreads();

    uint32_t qf[8][4];
    #pragma unroll
    for (int ks = 0; ks < 8; ks++)
        ldsm_x4(qf[ks][0], qf[ks][1], qf[ks][2], qf[ks][3],
                aQ + (uint32_t)ks * 32u);
    __syncthreads();   // all warps done reading Q smem before K buf0 overwrite

    ATT_ISSUE(0, sB0, sB2); CP_COMMIT();
    ATT_ISSUE(1, sB1, sB3); CP_COMMIT();

    float o[16][4];
    #pragma unroll
    for (int ni = 0; ni < 16; ni++)
        #pragma unroll
        for (int j = 0; j < 4; j++) o[ni][j] = 0.f;

    float m0 = -1e30f, m1 = -1e30f, l0 = 0.f, l1 = 0.f;
    const float scale2 = 0.12751744f;   // (1/sqrt(128)) * log2(e)

    for (int kt = 0; kt < 16; kt++) {
        CP_WAIT1();
        __syncthreads();

        const uint32_t fK = (kt & 1) ? fK1 : fK0;
        const uint32_t fV = (kt & 1) ? fV1 : fV0;

        float cs[8][4];
        #pragma unroll
        for (int ni = 0; ni < 8; ni++)
            #pragma unroll
            for (int j = 0; j < 4; j++) cs[ni][j] = 0.f;

        #pragma unroll
        for (int ks = 0; ks < 8; ks++) {
            const uint32_t koff = (uint32_t)ks * 32u;
            #pragma unroll
            for (int p = 0; p < 4; p++) {
                uint32_t b0, b1, b2, b3;
                ldsm_x4(b0, b1, b2, b3, fK + (uint32_t)(p * 16) * STB + koff);
                mma_f16(cs[2*p],   qf[ks][0], qf[ks][1], qf[ks][2], qf[ks][3], b0, b1);
                mma_f16(cs[2*p+1], qf[ks][0], qf[ks][1], qf[ks][2], qf[ks][3], b2, b3);
            }
        }
        #pragma unroll
        for (int ni = 0; ni < 8; ni++) {
            cs[ni][0] *= scale2; cs[ni][1] *= scale2;
            cs[ni][2] *= scale2; cs[ni][3] *= scale2;
        }

        float t0 = -1e30f, t1 = -1e30f;
        #pragma unroll
        for (int ni = 0; ni < 8; ni++) {
            t0 = fmaxf(t0, fmaxf(cs[ni][0], cs[ni][1]));
            t1 = fmaxf(t1, fmaxf(cs[ni][2], cs[ni][3]));
        }
        t0 = fmaxf(t0, __shfl_xor_sync(0xffffffffu, t0, 1));
        t0 = fmaxf(t0, __shfl_xor_sync(0xffffffffu, t0, 2));
        t1 = fmaxf(t1, __shfl_xor_sync(0xffffffffu, t1, 1));
        t1 = fmaxf(t1, __shfl_xor_sync(0xffffffffu, t1, 2));
        const float mn0 = fmaxf(m0, t0);
        const float mn1 = fmaxf(m1, t1);
        const float al0 = fexp2(m0 - mn0);
        const float al1 = fexp2(m1 - mn1);

        uint32_t plo[8], phi[8];
        float ps0 = 0.f, ps1 = 0.f;
        #pragma unroll
        for (int ni = 0; ni < 8; ni++) {
            __half2 d0 = __floats2half2_rn(cs[ni][0] - mn0, cs[ni][1] - mn0);
            __half2 d1 = __floats2half2_rn(cs[ni][2] - mn1, cs[ni][3] - mn1);
            plo[ni] = h2exp2_bits(*(uint32_t*)&d0);
            phi[ni] = h2exp2_bits(*(uint32_t*)&d1);
            __half2 p0 = *(__half2*)&plo[ni];
            __half2 p1 = *(__half2*)&phi[ni];
            ps0 += __low2float(p0) + __high2float(p0);
            ps1 += __low2float(p1) + __high2float(p1);
        }
        ps0 += __shfl_xor_sync(0xffffffffu, ps0, 1);
        ps0 += __shfl_xor_sync(0xffffffffu, ps0, 2);
        ps1 += __shfl_xor_sync(0xffffffffu, ps1, 1);
        ps1 += __shfl_xor_sync(0xffffffffu, ps1, 2);
        l0 = l0 * al0 + ps0;
        l1 = l1 * al1 + ps1;
        m0 = mn0;
        m1 = mn1;

        #pragma unroll
        for (int ni = 0; ni < 16; ni++) {
            o[ni][0] *= al0; o[ni][1] *= al0;
            o[ni][2] *= al1; o[ni][3] *= al1;
        }

        #pragma unroll
        for (int kc = 0; kc < 4; kc++) {
            const uint32_t a0 = plo[2*kc],   a1 = phi[2*kc];
            const uint32_t a2 = plo[2*kc+1], a3 = phi[2*kc+1];
            const uint32_t vro = (uint32_t)(kc * 16) * STB;
            #pragma unroll
            for (int np = 0; np < 8; np++) {
                uint32_t b0, b1, b2, b3;
                ldsm_x4_t(b0, b1, b2, b3, fV + vro + (uint32_t)np * 32u);
                mma_f16(o[2*np],   a0, a1, a2, a3, b0, b1);
                mma_f16(o[2*np+1], a0, a1, a2, a3, b2, b3);
            }
        }

        __syncthreads();
        if (kt + 2 < 16) {
            if (kt & 1) { ATT_ISSUE(kt + 2, sB1, sB3); }
            else        { ATT_ISSUE(kt + 2, sB0, sB2); }
        }
        CP_COMMIT();
    }
    #undef ATT_ISSUE

    const float inv0 = 1.f / l0;
    const float inv1 = 1.f / l1;
    #pragma unroll
    for (int ni = 0; ni < 16; ni++) {
        const int col = ni * 8 + 2 * qk;
        __half2 h0 = __floats2half2_rn(o[ni][0] * inv0, o[ni][1] * inv0);
        __half2 h1 = __floats2half2_rn(o[ni][2] * inv1, o[ni][3] * inv1);
        *(__half2*)(O + base + (size_t)(q0 + wm + qd)     * DM + col) = h0;
        *(__half2*)(O + base + (size_t)(q0 + wm + qd + 8) * DM + col) = h1;
    }
}

// ---------------------------------------------------------------------------
extern "C" void kernel_launch(void* const* d_in, const int* in_sizes, int n_in,
                              void* d_out, int out_size)
{
    const float* hidden = (const float*)d_in[0];
    const float* rope   = (const float*)d_in[1];
    const float* Wq     = (const float*)d_in[2];
    const float* Wk     = (const float*)d_in[3];
    const float* Wv     = (const float*)d_in[4];
    const float* Wo     = (const float*)d_in[5];
    const float* nqw    = (const float*)d_in[6];
    const float* nkw    = (const float*)d_in[7];
    float* out = (float*)d_out;

    float *q, *k;
    __half *xh, *kh, *vh, *aoh, *wqh, *wkh, *wvh, *woh;
    cudaGetSymbolAddress((void**)&q,   g_q);
    cudaGetSymbolAddress((void**)&k,   g_k);
    cudaGetSymbolAddress((void**)&xh,  g_xh);
    cudaGetSymbolAddress((void**)&kh,  g_kh);
    cudaGetSymbolAddress((void**)&vh,  g_vh);
    cudaGetSymbolAddress((void**)&aoh, g_aoh);
    cudaGetSymbolAddress((void**)&wqh, g_wqh);
    cudaGetSymbolAddress((void**)&wkh, g_wkh);
    cudaGetSymbolAddress((void**)&wvh, g_wvh);
    cudaGetSymbolAddress((void**)&woh, g_woh);

    const int nX4 = MROWS * DM / 4;
    const int nW4 = DM * DM / 4;
    zero_f32<<<(nX4 + 255) / 256, 256>>>(out, nX4);
    cvt_f32_f16<<<(nX4/2 + 255) / 256, 256>>>(hidden, xh, nX4/2);
    cvt4_f32_f16<<<(2 * nW4 + 255) / 256, 256>>>(Wq, Wk, Wv, Wo,
                                                 wqh, wkh, wvh, woh, nW4);

    cudaFuncSetAttribute(f16_gemm_kernel<false>, cudaFuncAttributeMaxDynamicSharedMemorySize, GEMM_SMEM);
    cudaFuncSetAttribute(f16_gemm_kernel<true>,  cudaFuncAttributeMaxDynamicSharedMemorySize, GEMM_SMEM);
    cudaFuncSetAttribute(attn_kernel, cudaFuncAttributeMaxDynamicSharedMemorySize, ATT_SMEM);

    // Fused QKV projection: q,k -> fp32; v -> fp16 directly
    f16_gemm_kernel<false><<<dim3(72, 16, 1), 256, GEMM_SMEM>>>(xh, wqh, wkh, wvh, q, k, vh);

    // Norm+RoPE: q,k fp32 -> fp16 (q-hat into xh)
    norm_rope_kernel<<<dim3(MROWS, NH/8), 256>>>(q, k, xh, kh, rope, nqw, nkw);

    attn_kernel<<<dim3(SSEQ/64, BB*NH), 128, ATT_SMEM>>>(xh, kh, vh, aoh);

    // Output projection, k-split 3, atomic-add epilogue
    f16_gemm_kernel<true><<<dim3(24, 16, 3), 256, GEMM_SMEM>>>(aoh, woh, woh, woh, out, out, aoh);
}